// round 7
// baseline (speedup 1.0000x reference)
#include <cuda_runtime.h>

// Inputs (metadata order):
//   d_in[0] = q                float32 [50000, 64]  (unused — scores cancel)
//   d_in[1] = k                float32 [50000, 64]  (unused)
//   d_in[2] = v                float32 [50000, 64]
//   d_in[3] = self_indices     int32   [800000]
//   d_in[4] = neighbor_indices int32   [800000]     (unused)
// Output: float32 [50000, 64]
//
// Math: out[n] = v[n] * sum_{e: self=n} attn_e; the per-segment attn sum is
// exactly (sum ex)/(sum ex) = 1 for non-empty segments and 0 for empty ones.
// So out[n] = v[n] * has_incoming_edge(n).
//
// Two kernels. Flag array's all-zero invariant is restored by the gather
// kernel (self-resetting), so no zeroing launch. Replay-safe.

#define N_NODES 50000
#define N_EDGES 800000
#define D 64

__device__ unsigned char g_flags[N_NODES];   // 50 KB, L2-resident

// K1: mark nodes appearing in self_indices.
// Test-and-set WITHOUT atomics: load first, store only if still 0. Duplicate
// edges (16/node average) mean almost all stores are skipped after the first
// waves, collapsing contended store traffic into the 50 KB flag region.
// Races are benign: worst case a redundant store of 1.
__global__ void mark_kernel(const int4* __restrict__ self4) {
    int i = blockIdx.x * blockDim.x + threadIdx.x;
    if (i < N_EDGES / 4) {
        int4 e = self4[i];
        // 4 independent byte loads issue together (MLP=4)
        unsigned char fx = g_flags[e.x];
        unsigned char fy = g_flags[e.y];
        unsigned char fz = g_flags[e.z];
        unsigned char fw = g_flags[e.w];
        if (!fx) g_flags[e.x] = 1;
        if (!fy) g_flags[e.y] = 1;
        if (!fz) g_flags[e.z] = 1;
        if (!fw) g_flags[e.w] = 1;
    }
}

// K2: out = flag ? v : 0, float4-coalesced, then reset flag.
// CRITICAL: v4 load is UNCONDITIONAL and independent of the flag load, so
// both are in flight simultaneously (MLP=2) instead of flag->predicate->load
// chaining. The select happens after both complete.
__global__ void gather_kernel(const float4* __restrict__ v4,
                              float4* __restrict__ out4) {
    int i = blockIdx.x * blockDim.x + threadIdx.x;
    if (i < N_NODES * (D / 4)) {
        int node = i >> 4;                       // D/4 == 16 float4 per node
        float4 val = v4[i];                      // always load — no predication
        unsigned char f = g_flags[node];         // independent, overlapped
        if (!f) val = make_float4(0.f, 0.f, 0.f, 0.f);
        out4[i] = val;
        if ((i & 15) == 0) g_flags[node] = 0;    // restore all-zero invariant
    }
}

extern "C" void kernel_launch(void* const* d_in, const int* in_sizes, int n_in,
                              void* d_out, int out_size) {
    const float* v = (const float*)d_in[2];
    const int* self_indices = (const int*)d_in[3];

    mark_kernel<<<(N_EDGES / 4 + 255) / 256, 256>>>((const int4*)self_indices);
    gather_kernel<<<(N_NODES * (D / 4) + 255) / 256, 256>>>(
        (const float4*)v, (float4*)d_out);
}